// round 6
// baseline (speedup 1.0000x reference)
#include <cuda_runtime.h>
#include <cuda_fp16.h>
#include <cstdint>

// Problem constants (fixed by setup_inputs)
#define Bb 4
#define Ts 4096
#define Dd 2560
#define Hh 10
#define BW 256
#define Mrows (Bb*Ts)   // 16384
#define NCHAN (Bb*Dd)   // 10240

// Scratch
__device__ float2 g_ax[(size_t)Bb * Ts * Dd];    // interleaved (a_eff, x_norm)
__device__ float  g_sp[Dd];                      // softplus(recurrent_param)
// Pre-packed, pre-swizzled fp16 tiles (exact smem layout, bulk-copied):
//   g_aP[tile(128r)][h][kt][r(128)][128B swizzled]   (84 MB)
//   g_wP[h][ny][kt][n(256)][128B swizzled]           (2.6 MB)
__device__ __align__(128) char g_aP[(size_t)Mrows * Dd * 2];
__device__ __align__(128) char g_wP[(size_t)Hh * 2 * 4 * 256 * 128];

// chunked-scan partials
#define CH 128
#define NCH (Ts / CH)    // 32
__device__ float g_P[NCH * NCHAN];
__device__ float g_h[NCH * NCHAN];
__device__ float g_H[NCH * NCHAN];

// ---------------------------------------------------------------------------
__device__ __forceinline__ uint32_t smem_u32(const void* p) {
    uint32_t a;
    asm("{ .reg .u64 t; cvta.to.shared.u64 t, %1; cvt.u32.u64 %0, t; }" : "=r"(a) : "l"(p));
    return a;
}
__device__ __forceinline__ void mma_f16(float* c, const uint32_t* a, const uint32_t* b) {
    asm volatile("mma.sync.aligned.m16n8k16.row.col.f32.f16.f16.f32 "
                 "{%0,%1,%2,%3}, {%4,%5,%6,%7}, {%8,%9}, {%0,%1,%2,%3};"
                 : "+f"(c[0]), "+f"(c[1]), "+f"(c[2]), "+f"(c[3])
                 : "r"(a[0]), "r"(a[1]), "r"(a[2]), "r"(a[3]), "r"(b[0]), "r"(b[1]));
}
#define MBAR_INIT(mbar, cnt) \
    asm volatile("mbarrier.init.shared.b64 [%0], %1;" :: "r"(mbar), "r"(cnt) : "memory")
#define MBAR_EXPECT(mbar, bytes) \
    asm volatile("mbarrier.arrive.expect_tx.shared.b64 _, [%0], %1;" :: "r"(mbar), "r"(bytes) : "memory")
#define MBAR_WAIT(mbar, par) do {                                              \
    uint32_t _m = (mbar), _p = (par), _d;                                      \
    asm volatile("{ .reg .pred p; mbarrier.try_wait.parity.acquire.cta.shared::cta.b64 p, [%1], %2; selp.b32 %0,1,0,p; }" \
                 : "=r"(_d) : "r"(_m), "r"(_p) : "memory");                    \
    if (!_d) {                                                                 \
        asm volatile("{ .reg .pred P1; WL_%=: mbarrier.try_wait.parity.acquire.cta.shared::cta.b64 P1, [%0], %1, 0x989680; @P1 bra.uni WD_%=; bra.uni WL_%=; WD_%=: }" \
                     :: "r"(_m), "r"(_p) : "memory");                          \
    } } while (0)
#define BULK_G2S(dst, src, sz, mbar) \
    asm volatile("cp.async.bulk.shared::cluster.global.mbarrier::complete_tx::bytes [%0], [%1], %2, [%3];" \
                 :: "r"(dst), "l"(src), "r"(sz), "r"(mbar) : "memory")

// ---------------------------------------------------------------------------
// Kernel 0: softplus table
// ---------------------------------------------------------------------------
__global__ void sp_kernel(const float* __restrict__ rp) {
    int d = blockIdx.x * blockDim.x + threadIdx.x;
    if (d < Dd) {
        float x = rp[d];
        g_sp[d] = (x > 20.0f) ? x : log1pf(__expf(x));
    }
}

// ---------------------------------------------------------------------------
// Kernel 0b: pack weights -> g_wP[h][ny][kt][n][128B swizzled], fp16,
// interleaved n = 2*j_local + gate.  One thread per 16B chunk.
// ---------------------------------------------------------------------------
__global__ __launch_bounds__(256) void wt_kernel(
    const float* __restrict__ wig, const float* __restrict__ wrg)
{
    int idx = blockIdx.x * 256 + threadIdx.x;   // Hh*2*4*256*8 = 163840
    int ch = idx & 7;
    int n  = (idx >> 3) & 255;
    int kt = (idx >> 11) & 3;
    int ny = (idx >> 13) & 1;
    int h  = idx >> 14;
    int j    = ny * 128 + (n >> 1);
    const float* src = (n & 1) ? wrg : wig;
    src += (size_t)h * BW * BW + j;             // + k*BW
    int kb = kt * 64 + ch * 8;
    __half2 v[4];
    #pragma unroll
    for (int i = 0; i < 4; i++)
        v[i] = __floats2half2_rn(src[(size_t)(kb + 2*i) * BW],
                                 src[(size_t)(kb + 2*i + 1) * BW]);
    size_t dst = ((((size_t)(h * 2 + ny) * 4 + kt) * 256 + n) * 128) + ((ch ^ (n & 7)) * 16);
    *(uint4*)(g_wP + dst) = *(uint4*)v;
}

// ---------------------------------------------------------------------------
// Kernel 0c: pack activations -> g_aP[tile][h][kt][r][128B swizzled], fp16.
// One block per row (320 threads = 320 chunks of 8 halfs).
// ---------------------------------------------------------------------------
__global__ __launch_bounds__(320) void cvt_kernel(const float* __restrict__ act) {
    int row = blockIdx.x;
    int k8  = threadIdx.x;            // 0..319
    int k   = k8 * 8;
    int h   = k >> 8;
    int kk  = k & 255;
    int kt  = kk >> 6;
    int ch  = (kk >> 3) & 7;
    int r    = row & 127;
    int tile = row >> 7;
    const float* s = act + (size_t)row * Dd + k;
    float4 v0 = *(const float4*)s;
    float4 v1 = *(const float4*)(s + 4);
    __half2 hv[4];
    hv[0] = __floats2half2_rn(v0.x, v0.y);
    hv[1] = __floats2half2_rn(v0.z, v0.w);
    hv[2] = __floats2half2_rn(v1.x, v1.y);
    hv[3] = __floats2half2_rn(v1.z, v1.w);
    size_t dst = ((((size_t)(tile * Hh + h) * 4 + kt) * 128 + r) * 128) + ((ch ^ (r & 7)) * 16);
    *(uint4*)(g_aP + dst) = *(uint4*)hv;
}

// ---------------------------------------------------------------------------
// Kernel 1: fp16 mma gates GEMM, bulk-copy loaded (8 UBLKCP per CTA),
// 4 stages fully resident in 192KB smem, mbarrier-per-stage, fused epilogue.
// CTA: 128 rows x 256 interleaved-cols; 8 warps 2(M) x 4(N), warp tile 64x64.
// ---------------------------------------------------------------------------
#define STG_A 16384
#define STG_W 32768
#define STG_B (STG_A + STG_W)          // 49152
#define SM_STAGE0 1024
#define SMEM_TOT (SM_STAGE0 + 4 * STG_B)   // 197632

__global__ __launch_bounds__(256, 1) void gates_mma_kernel(
    const float* __restrict__ act, const int* __restrict__ pos,
    const float* __restrict__ big, const float* __restrict__ brg)
{
    extern __shared__ char smc[];
    const uint32_t sb = smem_u32(smc);

    const int tid = threadIdx.x;
    const int wid = tid >> 5, lane = tid & 31;
    const int g = lane >> 2, t = lane & 3;
    const int wm = wid & 1;        // 64-row slab
    const int wn = wid >> 1;       // 64-col slab
    const int h  = blockIdx.z;
    const int ny = blockIdx.y;
    const int tile = blockIdx.x;
    const int rb = tile * 128;

    if (tid == 0) {
        #pragma unroll
        for (int s = 0; s < 4; s++) MBAR_INIT(sb + s * 8, 1);
    }
    __syncthreads();

    if (tid == 0) {
        const char* aSrc = g_aP + ((size_t)(tile * Hh + h) * 4) * STG_A;
        const char* wSrc = g_wP + ((size_t)(h * 2 + ny) * 4) * STG_W;
        #pragma unroll
        for (int s = 0; s < 4; s++) {
            uint32_t mb = sb + s * 8;
            uint32_t ds = sb + SM_STAGE0 + s * STG_B;
            MBAR_EXPECT(mb, STG_B);
            BULK_G2S(ds,        aSrc + (size_t)s * STG_A, STG_A, mb);
            BULK_G2S(ds + STG_A, wSrc + (size_t)s * STG_W, STG_W, mb);
        }
    }

    float acc[4][8][4];
    #pragma unroll
    for (int mt = 0; mt < 4; mt++)
        #pragma unroll
        for (int nt = 0; nt < 8; nt++)
            #pragma unroll
            for (int c = 0; c < 4; c++) acc[mt][nt][c] = 0.0f;

    const int aRow = (wm * 64 + g) * 128;   // byte offset of row (mt=0)
    const int wRow = (wn * 64 + g) * 128;

    #pragma unroll
    for (int kt = 0; kt < 4; kt++) {
        MBAR_WAIT(sb + kt * 8, 0);
        const char* Ab = smc + SM_STAGE0 + kt * STG_B;
        const char* Wb = Ab + STG_A;

        #pragma unroll
        for (int k16 = 0; k16 < 4; k16++) {
            const int c0 = (((k16 * 2)     ^ g) << 4) + 4 * t;
            const int c1 = (((k16 * 2 + 1) ^ g) << 4) + 4 * t;
            uint32_t bf[8][2];
            #pragma unroll
            for (int nt = 0; nt < 8; nt++) {
                const char* wp = Wb + wRow + nt * 1024;
                bf[nt][0] = *(const uint32_t*)(wp + c0);
                bf[nt][1] = *(const uint32_t*)(wp + c1);
            }
            #pragma unroll
            for (int mt = 0; mt < 4; mt++) {
                const char* ap = Ab + aRow + mt * 2048;
                uint32_t af[4];
                af[0] = *(const uint32_t*)(ap + c0);
                af[1] = *(const uint32_t*)(ap + 1024 + c0);
                af[2] = *(const uint32_t*)(ap + c1);
                af[3] = *(const uint32_t*)(ap + 1024 + c1);
                #pragma unroll
                for (int nt = 0; nt < 8; nt++)
                    mma_f16(acc[mt][nt], af, bf[nt]);
            }
        }
    }

    // -------- fused epilogue --------
    float bi[8], br[8], sp8[8];
    const int dg0 = h * BW + ny * 128 + wn * 32 + t;
    #pragma unroll
    for (int nt = 0; nt < 8; nt++) {
        int dg = dg0 + nt * 4;
        bi[nt]  = big[dg];
        br[nt]  = brg[dg];
        sp8[nt] = g_sp[dg];
    }

    #pragma unroll
    for (int mt = 0; mt < 4; mt++) {
        int r1 = rb + wm * 64 + mt * 16 + g;
        int r2 = r1 + 8;
        bool rs1 = (pos[r1] == 0);
        bool rs2 = (pos[r2] == 0);
        const float* a1p = act + (size_t)r1 * Dd;
        const float* a2p = act + (size_t)r2 * Dd;
        float2* o1 = g_ax + (size_t)r1 * Dd;
        float2* o2 = g_ax + (size_t)r2 * Dd;
        #pragma unroll
        for (int nt = 0; nt < 8; nt++) {
            int dg = dg0 + nt * 4;
            {
                float ig = 1.0f / (1.0f + __expf(-(acc[mt][nt][0] + bi[nt])));
                float rg = 1.0f / (1.0f + __expf(-(acc[mt][nt][1] + br[nt])));
                float a  = __expf(-8.0f * rg * sp8[nt]);
                float m  = sqrtf(fmaxf(fmaf(-a, a, 1.0f), 0.0f));
                float xn = a1p[dg] * ig * (rs1 ? 1.0f : m);
                o1[dg] = make_float2(rs1 ? 0.0f : a, xn);
            }
            {
                float ig = 1.0f / (1.0f + __expf(-(acc[mt][nt][2] + bi[nt])));
                float rg = 1.0f / (1.0f + __expf(-(acc[mt][nt][3] + br[nt])));
                float a  = __expf(-8.0f * rg * sp8[nt]);
                float m  = sqrtf(fmaxf(fmaf(-a, a, 1.0f), 0.0f));
                float xn = a2p[dg] * ig * (rs2 ? 1.0f : m);
                o2[dg] = make_float2(rs2 ? 0.0f : a, xn);
            }
        }
    }
}

// ---------------------------------------------------------------------------
// Kernel 2a: per-chunk local scan -> (product, local final state)
// ---------------------------------------------------------------------------
__global__ __launch_bounds__(128) void scan_part_kernel() {
    int ch = blockIdx.x * 128 + threadIdx.x;
    int c  = blockIdx.y;
    int b  = ch / Dd;
    int d  = ch - b * Dd;
    size_t base = (size_t)b * Ts * Dd + (size_t)c * CH * Dd + d;

    float P = 1.0f, hacc = 0.0f;
    #pragma unroll 1
    for (int t0 = 0; t0 < CH; t0 += 8) {
        float2 v[8];
        #pragma unroll
        for (int u = 0; u < 8; u++) v[u] = g_ax[base + (size_t)(t0 + u) * Dd];
        #pragma unroll
        for (int u = 0; u < 8; u++) {
            P *= v[u].x;
            hacc = fmaf(v[u].x, hacc, v[u].y);
        }
    }
    g_P[c * NCHAN + ch] = P;
    g_h[c * NCHAN + ch] = hacc;
}

// ---------------------------------------------------------------------------
// Kernel 2b: cross-chunk recurrence
// ---------------------------------------------------------------------------
__global__ __launch_bounds__(128) void scan_link_kernel() {
    int ch = blockIdx.x * 128 + threadIdx.x;
    float H = 0.0f;
    #pragma unroll
    for (int c = 0; c < NCH; c++) {
        g_H[c * NCHAN + ch] = H;
        H = fmaf(g_P[c * NCHAN + ch], H, g_h[c * NCHAN + ch]);
    }
}

// ---------------------------------------------------------------------------
// Kernel 2c: seeded local scan, write output
// ---------------------------------------------------------------------------
__global__ __launch_bounds__(128) void scan_final_kernel(float* __restrict__ out) {
    int ch = blockIdx.x * 128 + threadIdx.x;
    int c  = blockIdx.y;
    int b  = ch / Dd;
    int d  = ch - b * Dd;
    size_t base = (size_t)b * Ts * Dd + (size_t)c * CH * Dd + d;

    float hacc = g_H[c * NCHAN + ch];
    #pragma unroll 1
    for (int t0 = 0; t0 < CH; t0 += 8) {
        float2 v[8];
        #pragma unroll
        for (int u = 0; u < 8; u++) v[u] = g_ax[base + (size_t)(t0 + u) * Dd];
        #pragma unroll
        for (int u = 0; u < 8; u++) {
            hacc = fmaf(v[u].x, hacc, v[u].y);
            out[base + (size_t)(t0 + u) * Dd] = hacc;
        }
    }
}

// ---------------------------------------------------------------------------
extern "C" void kernel_launch(void* const* d_in, const int* in_sizes, int n_in,
                              void* d_out, int out_size) {
    const float* act = (const float*)d_in[0];
    const int*   pos = (const int*)  d_in[1];
    const float* wig = (const float*)d_in[2];
    const float* big = (const float*)d_in[3];
    const float* wrg = (const float*)d_in[4];
    const float* brg = (const float*)d_in[5];
    const float* rp  = (const float*)d_in[6];
    float* out = (float*)d_out;

    static int smem_set = 0;
    if (!smem_set) {
        cudaFuncSetAttribute(gates_mma_kernel,
                             cudaFuncAttributeMaxDynamicSharedMemorySize, SMEM_TOT);
        smem_set = 1;
    }

    sp_kernel<<<(Dd + 255) / 256, 256>>>(rp);
    wt_kernel<<<(Hh * 2 * 4 * 256 * 8) / 256, 256>>>(wig, wrg);
    cvt_kernel<<<Mrows, 320>>>(act);

    dim3 grid(Mrows / 128, 2, Hh);   // 2560 CTAs
    gates_mma_kernel<<<grid, 256, SMEM_TOT>>>(act, pos, big, brg);

    dim3 sgrid(NCHAN / 128, NCH);    // (80, 32)
    scan_part_kernel<<<sgrid, 128>>>();
    scan_link_kernel<<<NCHAN / 128, 128>>>();
    scan_final_kernel<<<sgrid, 128>>>(out);
}

// round 7
// speedup vs baseline: 1.4068x; 1.4068x over previous
#include <cuda_runtime.h>
#include <cuda_fp16.h>
#include <cstdint>

// Problem constants (fixed by setup_inputs)
#define Bb 4
#define Ts 4096
#define Dd 2560
#define Hh 10
#define BW 256
#define Mrows (Bb*Ts)   // 16384
#define NCHAN (Bb*Dd)   // 10240

// Scratch
__device__ float2 g_ax[(size_t)Bb * Ts * Dd];    // interleaved (a_eff, x_norm)
__device__ float  g_sp[Dd];                      // softplus(recurrent_param)
// Pre-packed, pre-swizzled fp16 tiles (exact smem layout, bulk-copied):
//   g_aP[tile(128r)][h][kt(4)][r(128)][128B swizzled]   (84 MB)
//   g_wP[h][nq(4)][kt(4)][n(128)][128B swizzled]        (2.6 MB)
__device__ __align__(128) char g_aP[(size_t)Mrows * Dd * 2];
__device__ __align__(128) char g_wP[(size_t)Hh * 4 * 4 * 128 * 128];

// chunked-scan partials
#define CH 128
#define NCH (Ts / CH)    // 32
__device__ float g_P[NCH * NCHAN];
__device__ float g_h[NCH * NCHAN];
__device__ float g_H[NCH * NCHAN];

// ---------------------------------------------------------------------------
__device__ __forceinline__ uint32_t smem_u32(const void* p) {
    uint32_t a;
    asm("{ .reg .u64 t; cvta.to.shared.u64 t, %1; cvt.u32.u64 %0, t; }" : "=r"(a) : "l"(p));
    return a;
}
__device__ __forceinline__ void mma_f16(float* c, const uint32_t* a, const uint32_t* b) {
    asm volatile("mma.sync.aligned.m16n8k16.row.col.f32.f16.f16.f32 "
                 "{%0,%1,%2,%3}, {%4,%5,%6,%7}, {%8,%9}, {%0,%1,%2,%3};"
                 : "+f"(c[0]), "+f"(c[1]), "+f"(c[2]), "+f"(c[3])
                 : "r"(a[0]), "r"(a[1]), "r"(a[2]), "r"(a[3]), "r"(b[0]), "r"(b[1]));
}
#define MBAR_INIT(mbar, cnt) \
    asm volatile("mbarrier.init.shared.b64 [%0], %1;" :: "r"(mbar), "r"(cnt) : "memory")
#define MBAR_EXPECT(mbar, bytes) \
    asm volatile("mbarrier.arrive.expect_tx.shared.b64 _, [%0], %1;" :: "r"(mbar), "r"(bytes) : "memory")
#define MBAR_WAIT(mbar, par) do {                                              \
    uint32_t _m = (mbar), _p = (par), _d;                                      \
    asm volatile("{ .reg .pred p; mbarrier.try_wait.parity.acquire.cta.shared::cta.b64 p, [%1], %2; selp.b32 %0,1,0,p; }" \
                 : "=r"(_d) : "r"(_m), "r"(_p) : "memory");                    \
    if (!_d) {                                                                 \
        asm volatile("{ .reg .pred P1; WL_%=: mbarrier.try_wait.parity.acquire.cta.shared::cta.b64 P1, [%0], %1, 0x989680; @P1 bra.uni WD_%=; bra.uni WL_%=; WD_%=: }" \
                     :: "r"(_m), "r"(_p) : "memory");                          \
    } } while (0)
#define BULK_G2S(dst, src, sz, mbar) \
    asm volatile("cp.async.bulk.shared::cluster.global.mbarrier::complete_tx::bytes [%0], [%1], %2, [%3];" \
                 :: "r"(dst), "l"(src), "r"(sz), "r"(mbar) : "memory")

// ---------------------------------------------------------------------------
// Kernel 0: softplus table
// ---------------------------------------------------------------------------
__global__ void sp_kernel(const float* __restrict__ rp) {
    int d = blockIdx.x * blockDim.x + threadIdx.x;
    if (d < Dd) {
        float x = rp[d];
        g_sp[d] = (x > 20.0f) ? x : log1pf(__expf(x));
    }
}

// ---------------------------------------------------------------------------
// Kernel 0b: pack weights -> g_wP[h][nq][kt][n(128)][128B swizzled], fp16,
// interleaved n = 2*j_local + gate, j = nq*64 + j_local. One thread per 16B.
// ---------------------------------------------------------------------------
__global__ __launch_bounds__(256) void wt_kernel(
    const float* __restrict__ wig, const float* __restrict__ wrg)
{
    int idx = blockIdx.x * 256 + threadIdx.x;   // Hh*4*4*128*8 = 163840
    int ch = idx & 7;
    int n  = (idx >> 3) & 127;
    int kt = (idx >> 10) & 3;
    int nq = (idx >> 12) & 3;
    int h  = idx >> 14;
    int j  = nq * 64 + (n >> 1);
    const float* src = (n & 1) ? wrg : wig;
    src += (size_t)h * BW * BW + j;             // + k*BW
    int kb = kt * 64 + ch * 8;
    __half2 v[4];
    #pragma unroll
    for (int i = 0; i < 4; i++)
        v[i] = __floats2half2_rn(src[(size_t)(kb + 2*i) * BW],
                                 src[(size_t)(kb + 2*i + 1) * BW]);
    size_t dst = ((((size_t)(h * 4 + nq) * 4 + kt) * 128 + n) * 128) + ((ch ^ (n & 7)) * 16);
    *(uint4*)(g_wP + dst) = *(uint4*)v;
}

// ---------------------------------------------------------------------------
// Kernel 0c: pack activations -> g_aP[tile][h][kt][r][128B swizzled], fp16.
// ---------------------------------------------------------------------------
__global__ __launch_bounds__(320) void cvt_kernel(const float* __restrict__ act) {
    int row = blockIdx.x;
    int k   = threadIdx.x * 8;
    int h   = k >> 8;
    int kk  = k & 255;
    int kt  = kk >> 6;
    int ch  = (kk >> 3) & 7;
    int r    = row & 127;
    int tile = row >> 7;
    const float* s = act + (size_t)row * Dd + k;
    float4 v0 = *(const float4*)s;
    float4 v1 = *(const float4*)(s + 4);
    __half2 hv[4];
    hv[0] = __floats2half2_rn(v0.x, v0.y);
    hv[1] = __floats2half2_rn(v0.z, v0.w);
    hv[2] = __floats2half2_rn(v1.x, v1.y);
    hv[3] = __floats2half2_rn(v1.z, v1.w);
    size_t dst = ((((size_t)(tile * Hh + h) * 4 + kt) * 128 + r) * 128) + ((ch ^ (r & 7)) * 16);
    *(uint4*)(g_aP + dst) = *(uint4*)hv;
}

// ---------------------------------------------------------------------------
// Kernel 1: fp16 mma gates GEMM, bulk-copy loaded, 3-buffer ring, 2 CTAs/SM.
// CTA: 128 rows x 128 interleaved-cols (64 j's); 8 warps 4(M) x 2(N),
// warp tile 32x64; acc 64 regs/thread.
// ---------------------------------------------------------------------------
#define STG_A 16384
#define STG_W 16384
#define STG_B (STG_A + STG_W)          // 32768
#define SM_ST0 1024
#define SMEM_TOT (SM_ST0 + 3 * STG_B)  // 99328

__global__ __launch_bounds__(256, 2) void gates_mma_kernel(
    const float* __restrict__ act, const int* __restrict__ pos,
    const float* __restrict__ big, const float* __restrict__ brg)
{
    extern __shared__ char smc[];
    const uint32_t sb = smem_u32(smc);

    const int tid = threadIdx.x;
    const int wid = tid >> 5, lane = tid & 31;
    const int g = lane >> 2, t = lane & 3;
    const int wm = wid & 3;        // 32-row slab
    const int wn = wid >> 2;       // 64-n slab
    const int h  = blockIdx.z;
    const int nq = blockIdx.y;
    const int tile = blockIdx.x;
    const int rb = tile * 128;

    if (tid == 0) {
        #pragma unroll
        for (int s = 0; s < 3; s++) MBAR_INIT(sb + s * 8, 1);
    }
    __syncthreads();

    const char* aSrc = g_aP + ((size_t)(tile * Hh + h) * 4) * STG_A;
    const char* wSrc = g_wP + ((size_t)(h * 4 + nq) * 4) * STG_W;
    if (tid == 0) {
        #pragma unroll
        for (int s = 0; s < 3; s++) {
            uint32_t mb = sb + s * 8;
            uint32_t ds = sb + SM_ST0 + s * STG_B;
            MBAR_EXPECT(mb, STG_B);
            BULK_G2S(ds,         aSrc + (size_t)s * STG_A, STG_A, mb);
            BULK_G2S(ds + STG_A, wSrc + (size_t)s * STG_W, STG_W, mb);
        }
    }

    float acc[2][8][4];
    #pragma unroll
    for (int mt = 0; mt < 2; mt++)
        #pragma unroll
        for (int nt = 0; nt < 8; nt++)
            #pragma unroll
            for (int c = 0; c < 4; c++) acc[mt][nt][c] = 0.0f;

    const int aRow = (wm * 32 + g) * 128;   // byte offset (mt=0 row)
    const int wRow = (wn * 64 + g) * 128;

    #pragma unroll
    for (int kt = 0; kt < 4; kt++) {
        MBAR_WAIT(sb + (kt % 3) * 8, (kt >= 3) ? 1 : 0);
        const char* Ab = smc + SM_ST0 + (kt % 3) * STG_B;
        const char* Wb = Ab + STG_A;

        #pragma unroll
        for (int k16 = 0; k16 < 4; k16++) {
            const int c0 = (((k16 * 2)     ^ g) << 4) + 4 * t;
            const int c1 = (((k16 * 2 + 1) ^ g) << 4) + 4 * t;
            uint32_t bf[8][2];
            #pragma unroll
            for (int nt = 0; nt < 8; nt++) {
                const char* wp = Wb + wRow + nt * 1024;
                bf[nt][0] = *(const uint32_t*)(wp + c0);
                bf[nt][1] = *(const uint32_t*)(wp + c1);
            }
            #pragma unroll
            for (int mt = 0; mt < 2; mt++) {
                const char* ap = Ab + aRow + mt * 2048;
                uint32_t af[4];
                af[0] = *(const uint32_t*)(ap + c0);
                af[1] = *(const uint32_t*)(ap + 1024 + c0);
                af[2] = *(const uint32_t*)(ap + c1);
                af[3] = *(const uint32_t*)(ap + 1024 + c1);
                #pragma unroll
                for (int nt = 0; nt < 8; nt++)
                    mma_f16(acc[mt][nt], af, bf[nt]);
            }
        }
        if (kt == 0) {     // buffer 0 free -> issue stage 3 into it
            __syncthreads();
            if (tid == 0) {
                MBAR_EXPECT(sb + 0, STG_B);
                BULK_G2S(sb + SM_ST0,         aSrc + (size_t)3 * STG_A, STG_A, sb + 0);
                BULK_G2S(sb + SM_ST0 + STG_A, wSrc + (size_t)3 * STG_W, STG_W, sb + 0);
            }
        }
    }

    // -------- fused epilogue --------
    float bi[8], br[8], sp8[8];
    const int dg0 = h * BW + nq * 64 + wn * 32 + t;
    #pragma unroll
    for (int nt = 0; nt < 8; nt++) {
        int dg = dg0 + nt * 4;
        bi[nt]  = big[dg];
        br[nt]  = brg[dg];
        sp8[nt] = g_sp[dg];
    }

    #pragma unroll
    for (int mt = 0; mt < 2; mt++) {
        int r1 = rb + wm * 32 + mt * 16 + g;
        int r2 = r1 + 8;
        bool rs1 = (pos[r1] == 0);
        bool rs2 = (pos[r2] == 0);
        const float* a1p = act + (size_t)r1 * Dd;
        const float* a2p = act + (size_t)r2 * Dd;
        float2* o1 = g_ax + (size_t)r1 * Dd;
        float2* o2 = g_ax + (size_t)r2 * Dd;
        #pragma unroll
        for (int nt = 0; nt < 8; nt++) {
            int dg = dg0 + nt * 4;
            {
                float ig = 1.0f / (1.0f + __expf(-(acc[mt][nt][0] + bi[nt])));
                float rg = 1.0f / (1.0f + __expf(-(acc[mt][nt][1] + br[nt])));
                float a  = __expf(-8.0f * rg * sp8[nt]);
                float m  = sqrtf(fmaxf(fmaf(-a, a, 1.0f), 0.0f));
                float xn = a1p[dg] * ig * (rs1 ? 1.0f : m);
                o1[dg] = make_float2(rs1 ? 0.0f : a, xn);
            }
            {
                float ig = 1.0f / (1.0f + __expf(-(acc[mt][nt][2] + bi[nt])));
                float rg = 1.0f / (1.0f + __expf(-(acc[mt][nt][3] + br[nt])));
                float a  = __expf(-8.0f * rg * sp8[nt]);
                float m  = sqrtf(fmaxf(fmaf(-a, a, 1.0f), 0.0f));
                float xn = a2p[dg] * ig * (rs2 ? 1.0f : m);
                o2[dg] = make_float2(rs2 ? 0.0f : a, xn);
            }
        }
    }
}

// ---------------------------------------------------------------------------
// Kernel 2a: per-chunk local scan -> (product, local final state)
// ---------------------------------------------------------------------------
__global__ __launch_bounds__(128) void scan_part_kernel() {
    int ch = blockIdx.x * 128 + threadIdx.x;
    int c  = blockIdx.y;
    int b  = ch / Dd;
    int d  = ch - b * Dd;
    size_t base = (size_t)b * Ts * Dd + (size_t)c * CH * Dd + d;

    float P = 1.0f, hacc = 0.0f;
    #pragma unroll 1
    for (int t0 = 0; t0 < CH; t0 += 8) {
        float2 v[8];
        #pragma unroll
        for (int u = 0; u < 8; u++) v[u] = g_ax[base + (size_t)(t0 + u) * Dd];
        #pragma unroll
        for (int u = 0; u < 8; u++) {
            P *= v[u].x;
            hacc = fmaf(v[u].x, hacc, v[u].y);
        }
    }
    g_P[c * NCHAN + ch] = P;
    g_h[c * NCHAN + ch] = hacc;
}

// ---------------------------------------------------------------------------
// Kernel 2b: cross-chunk recurrence
// ---------------------------------------------------------------------------
__global__ __launch_bounds__(128) void scan_link_kernel() {
    int ch = blockIdx.x * 128 + threadIdx.x;
    float H = 0.0f;
    #pragma unroll
    for (int c = 0; c < NCH; c++) {
        g_H[c * NCHAN + ch] = H;
        H = fmaf(g_P[c * NCHAN + ch], H, g_h[c * NCHAN + ch]);
    }
}

// ---------------------------------------------------------------------------
// Kernel 2c: seeded local scan, write output
// ---------------------------------------------------------------------------
__global__ __launch_bounds__(128) void scan_final_kernel(float* __restrict__ out) {
    int ch = blockIdx.x * 128 + threadIdx.x;
    int c  = blockIdx.y;
    int b  = ch / Dd;
    int d  = ch - b * Dd;
    size_t base = (size_t)b * Ts * Dd + (size_t)c * CH * Dd + d;

    float hacc = g_H[c * NCHAN + ch];
    #pragma unroll 1
    for (int t0 = 0; t0 < CH; t0 += 8) {
        float2 v[8];
        #pragma unroll
        for (int u = 0; u < 8; u++) v[u] = g_ax[base + (size_t)(t0 + u) * Dd];
        #pragma unroll
        for (int u = 0; u < 8; u++) {
            hacc = fmaf(v[u].x, hacc, v[u].y);
            out[base + (size_t)(t0 + u) * Dd] = hacc;
        }
    }
}

// ---------------------------------------------------------------------------
extern "C" void kernel_launch(void* const* d_in, const int* in_sizes, int n_in,
                              void* d_out, int out_size) {
    const float* act = (const float*)d_in[0];
    const int*   pos = (const int*)  d_in[1];
    const float* wig = (const float*)d_in[2];
    const float* big = (const float*)d_in[3];
    const float* wrg = (const float*)d_in[4];
    const float* brg = (const float*)d_in[5];
    const float* rp  = (const float*)d_in[6];
    float* out = (float*)d_out;

    static int smem_set = 0;
    if (!smem_set) {
        cudaFuncSetAttribute(gates_mma_kernel,
                             cudaFuncAttributeMaxDynamicSharedMemorySize, SMEM_TOT);
        smem_set = 1;
    }

    sp_kernel<<<(Dd + 255) / 256, 256>>>(rp);
    wt_kernel<<<(Hh * 4 * 4 * 128 * 8) / 256, 256>>>(wig, wrg);
    cvt_kernel<<<Mrows, 320>>>(act);

    dim3 grid(Mrows / 128, 4, Hh);   // 5120 CTAs
    gates_mma_kernel<<<grid, 256, SMEM_TOT>>>(act, pos, big, brg);

    dim3 sgrid(NCHAN / 128, NCH);    // (80, 32)
    scan_part_kernel<<<sgrid, 128>>>();
    scan_link_kernel<<<NCHAN / 128, 128>>>();
    scan_final_kernel<<<sgrid, 128>>>(out);
}

// round 8
// speedup vs baseline: 1.8836x; 1.3390x over previous
#include <cuda_runtime.h>
#include <cuda_fp16.h>
#include <cstdint>

// Problem constants (fixed by setup_inputs)
#define Bb 4
#define Ts 4096
#define Dd 2560
#define Hh 10
#define BW 256
#define Mrows (Bb*Ts)   // 16384
#define NCHAN (Bb*Dd)   // 10240

// Scratch
__device__ float2 g_ax[(size_t)Bb * Ts * Dd];    // interleaved (a_eff, x_norm)
__device__ float  g_sp[Dd];                      // softplus(recurrent_param)
// Pre-packed, pre-swizzled fp16 tiles (exact smem layout, bulk-copied):
//   g_aP[tile(64r)][h][kt(4)][r(64)][128B swizzled]   (84 MB)
//   g_wP[h][nq(4)][kt(4)][n(128)][128B swizzled]      (2.6 MB)
__device__ __align__(128) char g_aP[(size_t)Mrows * Dd * 2];
__device__ __align__(128) char g_wP[(size_t)Hh * 4 * 4 * 128 * 128];

// chunked-scan partials
#define CH 128
#define NCH (Ts / CH)    // 32
__device__ float g_P[NCH * NCHAN];
__device__ float g_h[NCH * NCHAN];
__device__ float g_H[NCH * NCHAN];

// ---------------------------------------------------------------------------
__device__ __forceinline__ uint32_t smem_u32(const void* p) {
    uint32_t a;
    asm("{ .reg .u64 t; cvta.to.shared.u64 t, %1; cvt.u32.u64 %0, t; }" : "=r"(a) : "l"(p));
    return a;
}
__device__ __forceinline__ void mma_f16(float* c, const uint32_t* a, const uint32_t* b) {
    asm volatile("mma.sync.aligned.m16n8k16.row.col.f32.f16.f16.f32 "
                 "{%0,%1,%2,%3}, {%4,%5,%6,%7}, {%8,%9}, {%0,%1,%2,%3};"
                 : "+f"(c[0]), "+f"(c[1]), "+f"(c[2]), "+f"(c[3])
                 : "r"(a[0]), "r"(a[1]), "r"(a[2]), "r"(a[3]), "r"(b[0]), "r"(b[1]));
}
#define MBAR_INIT(mbar, cnt) \
    asm volatile("mbarrier.init.shared.b64 [%0], %1;" :: "r"(mbar), "r"(cnt) : "memory")
#define MBAR_EXPECT(mbar, bytes) \
    asm volatile("mbarrier.arrive.expect_tx.shared.b64 _, [%0], %1;" :: "r"(mbar), "r"(bytes) : "memory")
#define MBAR_WAIT(mbar, par) do {                                              \
    uint32_t _m = (mbar), _p = (par), _d;                                      \
    asm volatile("{ .reg .pred p; mbarrier.try_wait.parity.acquire.cta.shared::cta.b64 p, [%1], %2; selp.b32 %0,1,0,p; }" \
                 : "=r"(_d) : "r"(_m), "r"(_p) : "memory");                    \
    if (!_d) {                                                                 \
        asm volatile("{ .reg .pred P1; WL_%=: mbarrier.try_wait.parity.acquire.cta.shared::cta.b64 P1, [%0], %1, 0x989680; @P1 bra.uni WD_%=; bra.uni WL_%=; WD_%=: }" \
                     :: "r"(_m), "r"(_p) : "memory");                          \
    } } while (0)
#define BULK_G2S(dst, src, sz, mbar) \
    asm volatile("cp.async.bulk.shared::cluster.global.mbarrier::complete_tx::bytes [%0], [%1], %2, [%3];" \
                 :: "r"(dst), "l"(src), "r"(sz), "r"(mbar) : "memory")

// ---------------------------------------------------------------------------
// Kernel 0: softplus table
// ---------------------------------------------------------------------------
__global__ void sp_kernel(const float* __restrict__ rp) {
    int d = blockIdx.x * blockDim.x + threadIdx.x;
    if (d < Dd) {
        float x = rp[d];
        g_sp[d] = (x > 20.0f) ? x : log1pf(__expf(x));
    }
}

// ---------------------------------------------------------------------------
// Kernel 0b: pack weights -> g_wP[h][nq][kt][n(128)][128B swizzled], fp16,
// interleaved n = 2*j_local + gate, j = nq*64 + j_local. One thread per 16B.
// ---------------------------------------------------------------------------
__global__ __launch_bounds__(256) void wt_kernel(
    const float* __restrict__ wig, const float* __restrict__ wrg)
{
    int idx = blockIdx.x * 256 + threadIdx.x;   // Hh*4*4*128*8 = 163840
    int ch = idx & 7;
    int n  = (idx >> 3) & 127;
    int kt = (idx >> 10) & 3;
    int nq = (idx >> 12) & 3;
    int h  = idx >> 14;
    int j  = nq * 64 + (n >> 1);
    const float* src = (n & 1) ? wrg : wig;
    src += (size_t)h * BW * BW + j;             // + k*BW
    int kb = kt * 64 + ch * 8;
    __half2 v[4];
    #pragma unroll
    for (int i = 0; i < 4; i++)
        v[i] = __floats2half2_rn(src[(size_t)(kb + 2*i) * BW],
                                 src[(size_t)(kb + 2*i + 1) * BW]);
    size_t dst = ((((size_t)(h * 4 + nq) * 4 + kt) * 128 + n) * 128) + ((ch ^ (n & 7)) * 16);
    *(uint4*)(g_wP + dst) = *(uint4*)v;
}

// ---------------------------------------------------------------------------
// Kernel 0c: pack activations -> g_aP[tile(64r)][h][kt][r(64)][128B swizzled].
// ---------------------------------------------------------------------------
__global__ __launch_bounds__(320) void cvt_kernel(const float* __restrict__ act) {
    int row = blockIdx.x;
    int k   = threadIdx.x * 8;
    int h   = k >> 8;
    int kk  = k & 255;
    int kt  = kk >> 6;
    int ch  = (kk >> 3) & 7;
    int r    = row & 63;
    int tile = row >> 6;
    const float* s = act + (size_t)row * Dd + k;
    float4 v0 = *(const float4*)s;
    float4 v1 = *(const float4*)(s + 4);
    __half2 hv[4];
    hv[0] = __floats2half2_rn(v0.x, v0.y);
    hv[1] = __floats2half2_rn(v0.z, v0.w);
    hv[2] = __floats2half2_rn(v1.x, v1.y);
    hv[3] = __floats2half2_rn(v1.z, v1.w);
    size_t dst = ((((size_t)(tile * Hh + h) * 4 + kt) * 64 + r) * 128) + ((ch ^ (r & 7)) * 16);
    *(uint4*)(g_aP + dst) = *(uint4*)hv;
}

// ---------------------------------------------------------------------------
// Kernel 1: fp16 mma gates GEMM, bulk-copy loaded, double-buffered, 4 CTAs/SM.
// CTA: 128 threads, tile 64 rows x 128 interleaved-cols (64 j's);
// 4 warps 2(M) x 2(N), warp tile 32x64; acc 64 regs/thread.
// ---------------------------------------------------------------------------
#define STG_A 8192
#define STG_W 16384
#define STG_B (STG_A + STG_W)          // 24576
#define SM_ST0 1024
#define SMEM_TOT (SM_ST0 + 2 * STG_B)  // 50176

__global__ __launch_bounds__(128, 4) void gates_mma_kernel(
    const float* __restrict__ act, const int* __restrict__ pos,
    const float* __restrict__ big, const float* __restrict__ brg)
{
    extern __shared__ char smc[];
    const uint32_t sb = smem_u32(smc);

    const int tid = threadIdx.x;
    const int wid = tid >> 5, lane = tid & 31;
    const int g = lane >> 2, t = lane & 3;
    const int wm = wid & 1;        // 32-row slab
    const int wn = wid >> 1;       // 64-n slab
    const int h  = blockIdx.z;
    const int nq = blockIdx.y;
    const int tile = blockIdx.x;
    const int rb = tile * 64;

    if (tid == 0) { MBAR_INIT(sb + 0, 1); MBAR_INIT(sb + 8, 1); }
    __syncthreads();

    const char* aSrc = g_aP + ((size_t)(tile * Hh + h) * 4) * STG_A;
    const char* wSrc = g_wP + ((size_t)(h * 4 + nq) * 4) * STG_W;
    if (tid == 0) {
        #pragma unroll
        for (int s = 0; s < 2; s++) {
            uint32_t mb = sb + s * 8;
            uint32_t ds = sb + SM_ST0 + s * STG_B;
            MBAR_EXPECT(mb, STG_B);
            BULK_G2S(ds,         aSrc + (size_t)s * STG_A, STG_A, mb);
            BULK_G2S(ds + STG_A, wSrc + (size_t)s * STG_W, STG_W, mb);
        }
    }

    float acc[2][8][4];
    #pragma unroll
    for (int mt = 0; mt < 2; mt++)
        #pragma unroll
        for (int nt = 0; nt < 8; nt++)
            #pragma unroll
            for (int c = 0; c < 4; c++) acc[mt][nt][c] = 0.0f;

    const int aRow = (wm * 32 + g) * 128;   // byte offset (mt=0 row)
    const int wRow = (wn * 64 + g) * 128;

    #pragma unroll
    for (int kt = 0; kt < 4; kt++) {
        MBAR_WAIT(sb + (kt & 1) * 8, (kt >> 1) & 1);
        const char* Ab = smc + SM_ST0 + (kt & 1) * STG_B;
        const char* Wb = Ab + STG_A;

        #pragma unroll
        for (int k16 = 0; k16 < 4; k16++) {
            const int c0 = (((k16 * 2)     ^ g) << 4) + 4 * t;
            const int c1 = (((k16 * 2 + 1) ^ g) << 4) + 4 * t;
            uint32_t bf[8][2];
            #pragma unroll
            for (int nt = 0; nt < 8; nt++) {
                const char* wp = Wb + wRow + nt * 1024;
                bf[nt][0] = *(const uint32_t*)(wp + c0);
                bf[nt][1] = *(const uint32_t*)(wp + c1);
            }
            #pragma unroll
            for (int mt = 0; mt < 2; mt++) {
                const char* ap = Ab + aRow + mt * 2048;
                uint32_t af[4];
                af[0] = *(const uint32_t*)(ap + c0);
                af[1] = *(const uint32_t*)(ap + 1024 + c0);
                af[2] = *(const uint32_t*)(ap + c1);
                af[3] = *(const uint32_t*)(ap + 1024 + c1);
                #pragma unroll
                for (int nt = 0; nt < 8; nt++)
                    mma_f16(acc[mt][nt], af, bf[nt]);
            }
        }
        if (kt < 2) {   // buffer kt free -> issue stage kt+2 into it
            __syncthreads();
            if (tid == 0) {
                uint32_t mb = sb + (kt & 1) * 8;
                uint32_t ds = sb + SM_ST0 + (kt & 1) * STG_B;
                MBAR_EXPECT(mb, STG_B);
                BULK_G2S(ds,         aSrc + (size_t)(kt + 2) * STG_A, STG_A, mb);
                BULK_G2S(ds + STG_A, wSrc + (size_t)(kt + 2) * STG_W, STG_W, mb);
            }
        }
    }

    // -------- fused epilogue --------
    float bi[8], br[8], sp8[8];
    const int dg0 = h * BW + nq * 64 + wn * 32 + t;
    #pragma unroll
    for (int nt = 0; nt < 8; nt++) {
        int dg = dg0 + nt * 4;
        bi[nt]  = big[dg];
        br[nt]  = brg[dg];
        sp8[nt] = g_sp[dg];
    }

    #pragma unroll
    for (int mt = 0; mt < 2; mt++) {
        int r1 = rb + wm * 32 + mt * 16 + g;
        int r2 = r1 + 8;
        bool rs1 = (pos[r1] == 0);
        bool rs2 = (pos[r2] == 0);
        const float* a1p = act + (size_t)r1 * Dd;
        const float* a2p = act + (size_t)r2 * Dd;
        float2* o1 = g_ax + (size_t)r1 * Dd;
        float2* o2 = g_ax + (size_t)r2 * Dd;
        #pragma unroll
        for (int nt = 0; nt < 8; nt++) {
            int dg = dg0 + nt * 4;
            {
                float ig = 1.0f / (1.0f + __expf(-(acc[mt][nt][0] + bi[nt])));
                float rg = 1.0f / (1.0f + __expf(-(acc[mt][nt][1] + br[nt])));
                float a  = __expf(-8.0f * rg * sp8[nt]);
                float m  = sqrtf(fmaxf(fmaf(-a, a, 1.0f), 0.0f));
                float xn = a1p[dg] * ig * (rs1 ? 1.0f : m);
                o1[dg] = make_float2(rs1 ? 0.0f : a, xn);
            }
            {
                float ig = 1.0f / (1.0f + __expf(-(acc[mt][nt][2] + bi[nt])));
                float rg = 1.0f / (1.0f + __expf(-(acc[mt][nt][3] + br[nt])));
                float a  = __expf(-8.0f * rg * sp8[nt]);
                float m  = sqrtf(fmaxf(fmaf(-a, a, 1.0f), 0.0f));
                float xn = a2p[dg] * ig * (rs2 ? 1.0f : m);
                o2[dg] = make_float2(rs2 ? 0.0f : a, xn);
            }
        }
    }
}

// ---------------------------------------------------------------------------
// Kernel 2a: per-chunk local scan -> (product, local final state)
// ---------------------------------------------------------------------------
__global__ __launch_bounds__(128) void scan_part_kernel() {
    int ch = blockIdx.x * 128 + threadIdx.x;
    int c  = blockIdx.y;
    int b  = ch / Dd;
    int d  = ch - b * Dd;
    size_t base = (size_t)b * Ts * Dd + (size_t)c * CH * Dd + d;

    float P = 1.0f, hacc = 0.0f;
    #pragma unroll 1
    for (int t0 = 0; t0 < CH; t0 += 8) {
        float2 v[8];
        #pragma unroll
        for (int u = 0; u < 8; u++) v[u] = g_ax[base + (size_t)(t0 + u) * Dd];
        #pragma unroll
        for (int u = 0; u < 8; u++) {
            P *= v[u].x;
            hacc = fmaf(v[u].x, hacc, v[u].y);
        }
    }
    g_P[c * NCHAN + ch] = P;
    g_h[c * NCHAN + ch] = hacc;
}

// ---------------------------------------------------------------------------
// Kernel 2b: cross-chunk recurrence
// ---------------------------------------------------------------------------
__global__ __launch_bounds__(128) void scan_link_kernel() {
    int ch = blockIdx.x * 128 + threadIdx.x;
    float H = 0.0f;
    #pragma unroll
    for (int c = 0; c < NCH; c++) {
        g_H[c * NCHAN + ch] = H;
        H = fmaf(g_P[c * NCHAN + ch], H, g_h[c * NCHAN + ch]);
    }
}

// ---------------------------------------------------------------------------
// Kernel 2c: seeded local scan, write output
// ---------------------------------------------------------------------------
__global__ __launch_bounds__(128) void scan_final_kernel(float* __restrict__ out) {
    int ch = blockIdx.x * 128 + threadIdx.x;
    int c  = blockIdx.y;
    int b  = ch / Dd;
    int d  = ch - b * Dd;
    size_t base = (size_t)b * Ts * Dd + (size_t)c * CH * Dd + d;

    float hacc = g_H[c * NCHAN + ch];
    #pragma unroll 1
    for (int t0 = 0; t0 < CH; t0 += 8) {
        float2 v[8];
        #pragma unroll
        for (int u = 0; u < 8; u++) v[u] = g_ax[base + (size_t)(t0 + u) * Dd];
        #pragma unroll
        for (int u = 0; u < 8; u++) {
            hacc = fmaf(v[u].x, hacc, v[u].y);
            out[base + (size_t)(t0 + u) * Dd] = hacc;
        }
    }
}

// ---------------------------------------------------------------------------
extern "C" void kernel_launch(void* const* d_in, const int* in_sizes, int n_in,
                              void* d_out, int out_size) {
    const float* act = (const float*)d_in[0];
    const int*   pos = (const int*)  d_in[1];
    const float* wig = (const float*)d_in[2];
    const float* big = (const float*)d_in[3];
    const float* wrg = (const float*)d_in[4];
    const float* brg = (const float*)d_in[5];
    const float* rp  = (const float*)d_in[6];
    float* out = (float*)d_out;

    static int smem_set = 0;
    if (!smem_set) {
        cudaFuncSetAttribute(gates_mma_kernel,
                             cudaFuncAttributeMaxDynamicSharedMemorySize, SMEM_TOT);
        smem_set = 1;
    }

    sp_kernel<<<(Dd + 255) / 256, 256>>>(rp);
    wt_kernel<<<(Hh * 4 * 4 * 128 * 8) / 256, 256>>>(wig, wrg);
    cvt_kernel<<<Mrows, 320>>>(act);

    dim3 grid(Mrows / 64, 4, Hh);    // (256, 4, 10) = 10240 CTAs
    gates_mma_kernel<<<grid, 128, SMEM_TOT>>>(act, pos, big, brg);

    dim3 sgrid(NCHAN / 128, NCH);    // (80, 32)
    scan_part_kernel<<<sgrid, 128>>>();
    scan_link_kernel<<<NCHAN / 128, 128>>>();
    scan_final_kernel<<<sgrid, 128>>>(out);
}

// round 9
// speedup vs baseline: 2.0375x; 1.0817x over previous
#include <cuda_runtime.h>
#include <cuda_fp16.h>
#include <cstdint>

// Problem constants (fixed by setup_inputs)
#define Bb 4
#define Ts 4096
#define Dd 2560
#define Hh 10
#define BW 256
#define Mrows (Bb*Ts)   // 16384
#define NCHAN (Bb*Dd)   // 10240

// Scratch
__device__ float2 g_ax[(size_t)Bb * Ts * Dd];    // interleaved (a_eff, x_norm)
__device__ float  g_sp[Dd];                      // softplus(recurrent_param)
// Pre-packed, pre-swizzled fp16 tiles (exact smem layout, bulk-copied):
//   g_aP[tile(64r)][h][kt(4)][r(64)][128B swizzled]   (84 MB)
//   g_wP[h][nq(4)][kt(4)][n(128)][128B swizzled]      (2.6 MB)
__device__ __align__(128) char g_aP[(size_t)Mrows * Dd * 2];
__device__ __align__(128) char g_wP[(size_t)Hh * 4 * 4 * 128 * 128];

// chunked-scan partials
#define CH 128
#define NCH (Ts / CH)    // 32
__device__ float g_P[NCH * NCHAN];
__device__ float g_h[NCH * NCHAN];
__device__ float g_H[NCH * NCHAN];

// ---------------------------------------------------------------------------
__device__ __forceinline__ uint32_t smem_u32(const void* p) {
    uint32_t a;
    asm("{ .reg .u64 t; cvta.to.shared.u64 t, %1; cvt.u32.u64 %0, t; }" : "=r"(a) : "l"(p));
    return a;
}
__device__ __forceinline__ void mma_f16(float* c, const uint32_t* a, const uint32_t* b) {
    asm volatile("mma.sync.aligned.m16n8k16.row.col.f32.f16.f16.f32 "
                 "{%0,%1,%2,%3}, {%4,%5,%6,%7}, {%8,%9}, {%0,%1,%2,%3};"
                 : "+f"(c[0]), "+f"(c[1]), "+f"(c[2]), "+f"(c[3])
                 : "r"(a[0]), "r"(a[1]), "r"(a[2]), "r"(a[3]), "r"(b[0]), "r"(b[1]));
}
#define MBAR_INIT(mbar, cnt) \
    asm volatile("mbarrier.init.shared.b64 [%0], %1;" :: "r"(mbar), "r"(cnt) : "memory")
#define MBAR_EXPECT(mbar, bytes) \
    asm volatile("mbarrier.arrive.expect_tx.shared.b64 _, [%0], %1;" :: "r"(mbar), "r"(bytes) : "memory")
#define MBAR_WAIT(mbar, par) do {                                              \
    uint32_t _m = (mbar), _p = (par), _d;                                      \
    asm volatile("{ .reg .pred p; mbarrier.try_wait.parity.acquire.cta.shared::cta.b64 p, [%1], %2; selp.b32 %0,1,0,p; }" \
                 : "=r"(_d) : "r"(_m), "r"(_p) : "memory");                    \
    if (!_d) {                                                                 \
        asm volatile("{ .reg .pred P1; WL_%=: mbarrier.try_wait.parity.acquire.cta.shared::cta.b64 P1, [%0], %1, 0x989680; @P1 bra.uni WD_%=; bra.uni WL_%=; WD_%=: }" \
                     :: "r"(_m), "r"(_p) : "memory");                          \
    } } while (0)
#define BULK_G2S(dst, src, sz, mbar) \
    asm volatile("cp.async.bulk.shared::cluster.global.mbarrier::complete_tx::bytes [%0], [%1], %2, [%3];" \
                 :: "r"(dst), "l"(src), "r"(sz), "r"(mbar) : "memory")

// ---------------------------------------------------------------------------
// Kernel 0: softplus table
// ---------------------------------------------------------------------------
__global__ void sp_kernel(const float* __restrict__ rp) {
    int d = blockIdx.x * blockDim.x + threadIdx.x;
    if (d < Dd) {
        float x = rp[d];
        g_sp[d] = (x > 20.0f) ? x : log1pf(__expf(x));
    }
}

// ---------------------------------------------------------------------------
// Kernel 0b: pack weights -> g_wP[h][nq][kt][n(128)][128B swizzled], fp16,
// interleaved n = 2*j_local + gate, j = nq*64 + j_local. One thread per 16B.
// ---------------------------------------------------------------------------
__global__ __launch_bounds__(256) void wt_kernel(
    const float* __restrict__ wig, const float* __restrict__ wrg)
{
    int idx = blockIdx.x * 256 + threadIdx.x;   // Hh*4*4*128*8 = 163840
    int ch = idx & 7;
    int n  = (idx >> 3) & 127;
    int kt = (idx >> 10) & 3;
    int nq = (idx >> 12) & 3;
    int h  = idx >> 14;
    int j  = nq * 64 + (n >> 1);
    const float* src = (n & 1) ? wrg : wig;
    src += (size_t)h * BW * BW + j;             // + k*BW
    int kb = kt * 64 + ch * 8;
    __half2 v[4];
    #pragma unroll
    for (int i = 0; i < 4; i++)
        v[i] = __floats2half2_rn(src[(size_t)(kb + 2*i) * BW],
                                 src[(size_t)(kb + 2*i + 1) * BW]);
    size_t dst = ((((size_t)(h * 4 + nq) * 4 + kt) * 128 + n) * 128) + ((ch ^ (n & 7)) * 16);
    *(uint4*)(g_wP + dst) = *(uint4*)v;
}

// ---------------------------------------------------------------------------
// Kernel 0c: pack activations -> g_aP[tile(64r)][h][kt][r(64)][128B swizzled].
// ---------------------------------------------------------------------------
__global__ __launch_bounds__(320) void cvt_kernel(const float* __restrict__ act) {
    int row = blockIdx.x;
    int k   = threadIdx.x * 8;
    int h   = k >> 8;
    int kk  = k & 255;
    int kt  = kk >> 6;
    int ch  = (kk >> 3) & 7;
    int r    = row & 63;
    int tile = row >> 6;
    const float* s = act + (size_t)row * Dd + k;
    float4 v0 = *(const float4*)s;
    float4 v1 = *(const float4*)(s + 4);
    __half2 hv[4];
    hv[0] = __floats2half2_rn(v0.x, v0.y);
    hv[1] = __floats2half2_rn(v0.z, v0.w);
    hv[2] = __floats2half2_rn(v1.x, v1.y);
    hv[3] = __floats2half2_rn(v1.z, v1.w);
    size_t dst = ((((size_t)(tile * Hh + h) * 4 + kt) * 64 + r) * 128) + ((ch ^ (r & 7)) * 16);
    *(uint4*)(g_aP + dst) = *(uint4*)hv;
}

// ---------------------------------------------------------------------------
// Kernel 1: fp16 mma gates GEMM, bulk-copy loaded, double-buffered, 3 CTAs/SM
// of 8 warps each (24 warps/SM). CTA: 256 threads, tile 64 rows x 128
// interleaved-cols; 8 warps 2(M) x 4(N), warp tile 32x32; acc 32 regs/thread.
// ---------------------------------------------------------------------------
#define STG_A 8192
#define STG_W 16384
#define STG_B (STG_A + STG_W)          // 24576
#define SM_ST0 1024
#define SMEM_TOT (SM_ST0 + 2 * STG_B)  // 50176

__global__ __launch_bounds__(256, 3) void gates_mma_kernel(
    const float* __restrict__ act, const int* __restrict__ pos,
    const float* __restrict__ big, const float* __restrict__ brg)
{
    extern __shared__ char smc[];
    const uint32_t sb = smem_u32(smc);

    const int tid = threadIdx.x;
    const int wid = tid >> 5, lane = tid & 31;
    const int g = lane >> 2, t = lane & 3;
    const int wm = wid & 1;        // 32-row slab
    const int wn = wid >> 1;       // 0..3 -> 32-col slab (16 j's)
    const int h  = blockIdx.z;
    const int nq = blockIdx.y;
    const int tile = blockIdx.x;
    const int rb = tile * 64;

    if (tid == 0) { MBAR_INIT(sb + 0, 1); MBAR_INIT(sb + 8, 1); }
    __syncthreads();

    const char* aSrc = g_aP + ((size_t)(tile * Hh + h) * 4) * STG_A;
    const char* wSrc = g_wP + ((size_t)(h * 4 + nq) * 4) * STG_W;
    if (tid == 0) {
        #pragma unroll
        for (int s = 0; s < 2; s++) {
            uint32_t mb = sb + s * 8;
            uint32_t ds = sb + SM_ST0 + s * STG_B;
            MBAR_EXPECT(mb, STG_B);
            BULK_G2S(ds,         aSrc + (size_t)s * STG_A, STG_A, mb);
            BULK_G2S(ds + STG_A, wSrc + (size_t)s * STG_W, STG_W, mb);
        }
    }

    float acc[2][4][4];
    #pragma unroll
    for (int mt = 0; mt < 2; mt++)
        #pragma unroll
        for (int nt = 0; nt < 4; nt++)
            #pragma unroll
            for (int c = 0; c < 4; c++) acc[mt][nt][c] = 0.0f;

    const int aRow = (wm * 32 + g) * 128;   // byte offset (mt=0 row)
    const int wRow = (wn * 32 + g) * 128;

    #pragma unroll
    for (int kt = 0; kt < 4; kt++) {
        MBAR_WAIT(sb + (kt & 1) * 8, (kt >> 1) & 1);
        const char* Ab = smc + SM_ST0 + (kt & 1) * STG_B;
        const char* Wb = Ab + STG_A;

        #pragma unroll
        for (int k16 = 0; k16 < 4; k16++) {
            const int c0 = (((k16 * 2)     ^ g) << 4) + 4 * t;
            const int c1 = (((k16 * 2 + 1) ^ g) << 4) + 4 * t;
            uint32_t bf[4][2];
            #pragma unroll
            for (int nt = 0; nt < 4; nt++) {
                const char* wp = Wb + wRow + nt * 1024;
                bf[nt][0] = *(const uint32_t*)(wp + c0);
                bf[nt][1] = *(const uint32_t*)(wp + c1);
            }
            #pragma unroll
            for (int mt = 0; mt < 2; mt++) {
                const char* ap = Ab + aRow + mt * 2048;
                uint32_t af[4];
                af[0] = *(const uint32_t*)(ap + c0);
                af[1] = *(const uint32_t*)(ap + 1024 + c0);
                af[2] = *(const uint32_t*)(ap + c1);
                af[3] = *(const uint32_t*)(ap + 1024 + c1);
                #pragma unroll
                for (int nt = 0; nt < 4; nt++)
                    mma_f16(acc[mt][nt], af, bf[nt]);
            }
        }
        if (kt < 2) {   // buffer kt free -> issue stage kt+2 into it
            __syncthreads();
            if (tid == 0) {
                uint32_t mb = sb + (kt & 1) * 8;
                uint32_t ds = sb + SM_ST0 + (kt & 1) * STG_B;
                MBAR_EXPECT(mb, STG_B);
                BULK_G2S(ds,         aSrc + (size_t)(kt + 2) * STG_A, STG_A, mb);
                BULK_G2S(ds + STG_A, wSrc + (size_t)(kt + 2) * STG_W, STG_W, mb);
            }
        }
    }

    // -------- fused epilogue --------
    // thread's j for nt: j = nq*64 + wn*16 + nt*4 + t ; gates (c0,c1)/(c2,c3)
    float bi[4], br[4], sp4[4];
    const int dg0 = h * BW + nq * 64 + wn * 16 + t;
    #pragma unroll
    for (int nt = 0; nt < 4; nt++) {
        int dg = dg0 + nt * 4;
        bi[nt]  = big[dg];
        br[nt]  = brg[dg];
        sp4[nt] = g_sp[dg];
    }

    #pragma unroll
    for (int mt = 0; mt < 2; mt++) {
        int r1 = rb + wm * 32 + mt * 16 + g;
        int r2 = r1 + 8;
        bool rs1 = (pos[r1] == 0);
        bool rs2 = (pos[r2] == 0);
        const float* a1p = act + (size_t)r1 * Dd;
        const float* a2p = act + (size_t)r2 * Dd;
        float2* o1 = g_ax + (size_t)r1 * Dd;
        float2* o2 = g_ax + (size_t)r2 * Dd;
        #pragma unroll
        for (int nt = 0; nt < 4; nt++) {
            int dg = dg0 + nt * 4;
            {
                float ig = 1.0f / (1.0f + __expf(-(acc[mt][nt][0] + bi[nt])));
                float rg = 1.0f / (1.0f + __expf(-(acc[mt][nt][1] + br[nt])));
                float a  = __expf(-8.0f * rg * sp4[nt]);
                float m  = sqrtf(fmaxf(fmaf(-a, a, 1.0f), 0.0f));
                float xn = a1p[dg] * ig * (rs1 ? 1.0f : m);
                o1[dg] = make_float2(rs1 ? 0.0f : a, xn);
            }
            {
                float ig = 1.0f / (1.0f + __expf(-(acc[mt][nt][2] + bi[nt])));
                float rg = 1.0f / (1.0f + __expf(-(acc[mt][nt][3] + br[nt])));
                float a  = __expf(-8.0f * rg * sp4[nt]);
                float m  = sqrtf(fmaxf(fmaf(-a, a, 1.0f), 0.0f));
                float xn = a2p[dg] * ig * (rs2 ? 1.0f : m);
                o2[dg] = make_float2(rs2 ? 0.0f : a, xn);
            }
        }
    }
}

// ---------------------------------------------------------------------------
// Kernel 2a: per-chunk local scan -> (product, local final state)
// ---------------------------------------------------------------------------
__global__ __launch_bounds__(128) void scan_part_kernel() {
    int ch = blockIdx.x * 128 + threadIdx.x;
    int c  = blockIdx.y;
    int b  = ch / Dd;
    int d  = ch - b * Dd;
    size_t base = (size_t)b * Ts * Dd + (size_t)c * CH * Dd + d;

    float P = 1.0f, hacc = 0.0f;
    #pragma unroll 1
    for (int t0 = 0; t0 < CH; t0 += 8) {
        float2 v[8];
        #pragma unroll
        for (int u = 0; u < 8; u++) v[u] = g_ax[base + (size_t)(t0 + u) * Dd];
        #pragma unroll
        for (int u = 0; u < 8; u++) {
            P *= v[u].x;
            hacc = fmaf(v[u].x, hacc, v[u].y);
        }
    }
    g_P[c * NCHAN + ch] = P;
    g_h[c * NCHAN + ch] = hacc;
}

// ---------------------------------------------------------------------------
// Kernel 2b: cross-chunk recurrence
// ---------------------------------------------------------------------------
__global__ __launch_bounds__(128) void scan_link_kernel() {
    int ch = blockIdx.x * 128 + threadIdx.x;
    float H = 0.0f;
    #pragma unroll
    for (int c = 0; c < NCH; c++) {
        g_H[c * NCHAN + ch] = H;
        H = fmaf(g_P[c * NCHAN + ch], H, g_h[c * NCHAN + ch]);
    }
}

// ---------------------------------------------------------------------------
// Kernel 2c: seeded local scan, write output
// ---------------------------------------------------------------------------
__global__ __launch_bounds__(128) void scan_final_kernel(float* __restrict__ out) {
    int ch = blockIdx.x * 128 + threadIdx.x;
    int c  = blockIdx.y;
    int b  = ch / Dd;
    int d  = ch - b * Dd;
    size_t base = (size_t)b * Ts * Dd + (size_t)c * CH * Dd + d;

    float hacc = g_H[c * NCHAN + ch];
    #pragma unroll 1
    for (int t0 = 0; t0 < CH; t0 += 8) {
        float2 v[8];
        #pragma unroll
        for (int u = 0; u < 8; u++) v[u] = g_ax[base + (size_t)(t0 + u) * Dd];
        #pragma unroll
        for (int u = 0; u < 8; u++) {
            hacc = fmaf(v[u].x, hacc, v[u].y);
            out[base + (size_t)(t0 + u) * Dd] = hacc;
        }
    }
}

// ---------------------------------------------------------------------------
extern "C" void kernel_launch(void* const* d_in, const int* in_sizes, int n_in,
                              void* d_out, int out_size) {
    const float* act = (const float*)d_in[0];
    const int*   pos = (const int*)  d_in[1];
    const float* wig = (const float*)d_in[2];
    const float* big = (const float*)d_in[3];
    const float* wrg = (const float*)d_in[4];
    const float* brg = (const float*)d_in[5];
    const float* rp  = (const float*)d_in[6];
    float* out = (float*)d_out;

    static int smem_set = 0;
    if (!smem_set) {
        cudaFuncSetAttribute(gates_mma_kernel,
                             cudaFuncAttributeMaxDynamicSharedMemorySize, SMEM_TOT);
        smem_set = 1;
    }

    sp_kernel<<<(Dd + 255) / 256, 256>>>(rp);
    wt_kernel<<<(Hh * 4 * 4 * 128 * 8) / 256, 256>>>(wig, wrg);
    cvt_kernel<<<Mrows, 320>>>(act);

    dim3 grid(Mrows / 64, 4, Hh);    // (256, 4, 10) = 10240 CTAs
    gates_mma_kernel<<<grid, 256, SMEM_TOT>>>(act, pos, big, brg);

    dim3 sgrid(NCHAN / 128, NCH);    // (80, 32)
    scan_part_kernel<<<sgrid, 128>>>();
    scan_link_kernel<<<NCHAN / 128, 128>>>();
    scan_final_kernel<<<sgrid, 128>>>(out);
}

// round 10
// speedup vs baseline: 2.1843x; 1.0721x over previous
#include <cuda_runtime.h>
#include <cuda_fp16.h>
#include <cstdint>

// Problem constants (fixed by setup_inputs)
#define Bb 4
#define Ts 4096
#define Dd 2560
#define Hh 10
#define BW 256
#define Mrows (Bb*Ts)   // 16384
#define NCHAN (Bb*Dd)   // 10240

// Scratch
__device__ float2 g_ax[(size_t)Bb * Ts * Dd];    // interleaved (a_eff, x_norm)
__device__ float  g_sp[Dd];                      // softplus(recurrent_param)
// Pre-packed, pre-swizzled fp16 tiles (exact smem layout, bulk-copied):
//   g_aP[tile(64r)][h][kt(4)][r(64)][128B swizzled]   (84 MB)
//   g_wP[h][nq(4)][kt(4)][n(128)][128B swizzled]      (2.6 MB)
__device__ __align__(128) char g_aP[(size_t)Mrows * Dd * 2];
__device__ __align__(128) char g_wP[(size_t)Hh * 4 * 4 * 128 * 128];

// chunked-scan partials
#define CH 128
#define NCH (Ts / CH)    // 32
__device__ float g_P[NCH * NCHAN];
__device__ float g_h[NCH * NCHAN];
__device__ float g_H[NCH * NCHAN];

// ---------------------------------------------------------------------------
__device__ __forceinline__ uint32_t smem_u32(const void* p) {
    uint32_t a;
    asm("{ .reg .u64 t; cvta.to.shared.u64 t, %1; cvt.u32.u64 %0, t; }" : "=r"(a) : "l"(p));
    return a;
}
__device__ __forceinline__ void mma_f16(float* c, const uint32_t* a,
                                        uint32_t b0, uint32_t b1) {
    asm volatile("mma.sync.aligned.m16n8k16.row.col.f32.f16.f16.f32 "
                 "{%0,%1,%2,%3}, {%4,%5,%6,%7}, {%8,%9}, {%0,%1,%2,%3};"
                 : "+f"(c[0]), "+f"(c[1]), "+f"(c[2]), "+f"(c[3])
                 : "r"(a[0]), "r"(a[1]), "r"(a[2]), "r"(a[3]), "r"(b0), "r"(b1));
}
__device__ __forceinline__ void ldm_x4(uint32_t* r, uint32_t addr) {
    asm volatile("ldmatrix.sync.aligned.m8n8.x4.shared.b16 {%0,%1,%2,%3}, [%4];"
                 : "=r"(r[0]), "=r"(r[1]), "=r"(r[2]), "=r"(r[3]) : "r"(addr));
}
#define MBAR_INIT(mbar, cnt) \
    asm volatile("mbarrier.init.shared.b64 [%0], %1;" :: "r"(mbar), "r"(cnt) : "memory")
#define MBAR_EXPECT(mbar, bytes) \
    asm volatile("mbarrier.arrive.expect_tx.shared.b64 _, [%0], %1;" :: "r"(mbar), "r"(bytes) : "memory")
#define MBAR_WAIT(mbar, par) do {                                              \
    uint32_t _m = (mbar), _p = (par), _d;                                      \
    asm volatile("{ .reg .pred p; mbarrier.try_wait.parity.acquire.cta.shared::cta.b64 p, [%1], %2; selp.b32 %0,1,0,p; }" \
                 : "=r"(_d) : "r"(_m), "r"(_p) : "memory");                    \
    if (!_d) {                                                                 \
        asm volatile("{ .reg .pred P1; WL_%=: mbarrier.try_wait.parity.acquire.cta.shared::cta.b64 P1, [%0], %1, 0x989680; @P1 bra.uni WD_%=; bra.uni WL_%=; WD_%=: }" \
                     :: "r"(_m), "r"(_p) : "memory");                          \
    } } while (0)
#define BULK_G2S(dst, src, sz, mbar) \
    asm volatile("cp.async.bulk.shared::cluster.global.mbarrier::complete_tx::bytes [%0], [%1], %2, [%3];" \
                 :: "r"(dst), "l"(src), "r"(sz), "r"(mbar) : "memory")

// ---------------------------------------------------------------------------
// Kernel 0: softplus table
// ---------------------------------------------------------------------------
__global__ void sp_kernel(const float* __restrict__ rp) {
    int d = blockIdx.x * blockDim.x + threadIdx.x;
    if (d < Dd) {
        float x = rp[d];
        g_sp[d] = (x > 20.0f) ? x : log1pf(__expf(x));
    }
}

// ---------------------------------------------------------------------------
// Kernel 0b: pack weights -> g_wP[h][nq][kt][n(128)][128B swizzled], fp16,
// interleaved n = 2*j_local + gate, j = nq*64 + j_local. One thread per 16B.
// ---------------------------------------------------------------------------
__global__ __launch_bounds__(256) void wt_kernel(
    const float* __restrict__ wig, const float* __restrict__ wrg)
{
    int idx = blockIdx.x * 256 + threadIdx.x;   // Hh*4*4*128*8 = 163840
    int ch = idx & 7;
    int n  = (idx >> 3) & 127;
    int kt = (idx >> 10) & 3;
    int nq = (idx >> 12) & 3;
    int h  = idx >> 14;
    int j  = nq * 64 + (n >> 1);
    const float* src = (n & 1) ? wrg : wig;
    src += (size_t)h * BW * BW + j;             // + k*BW
    int kb = kt * 64 + ch * 8;
    __half2 v[4];
    #pragma unroll
    for (int i = 0; i < 4; i++)
        v[i] = __floats2half2_rn(src[(size_t)(kb + 2*i) * BW],
                                 src[(size_t)(kb + 2*i + 1) * BW]);
    size_t dst = ((((size_t)(h * 4 + nq) * 4 + kt) * 128 + n) * 128) + ((ch ^ (n & 7)) * 16);
    *(uint4*)(g_wP + dst) = *(uint4*)v;
}

// ---------------------------------------------------------------------------
// Kernel 0c: pack activations -> g_aP[tile(64r)][h][kt][r(64)][128B swizzled].
// ---------------------------------------------------------------------------
__global__ __launch_bounds__(320) void cvt_kernel(const float* __restrict__ act) {
    int row = blockIdx.x;
    int k   = threadIdx.x * 8;
    int h   = k >> 8;
    int kk  = k & 255;
    int kt  = kk >> 6;
    int ch  = (kk >> 3) & 7;
    int r    = row & 63;
    int tile = row >> 6;
    const float* s = act + (size_t)row * Dd + k;
    float4 v0 = *(const float4*)s;
    float4 v1 = *(const float4*)(s + 4);
    __half2 hv[4];
    hv[0] = __floats2half2_rn(v0.x, v0.y);
    hv[1] = __floats2half2_rn(v0.z, v0.w);
    hv[2] = __floats2half2_rn(v1.x, v1.y);
    hv[3] = __floats2half2_rn(v1.z, v1.w);
    size_t dst = ((((size_t)(tile * Hh + h) * 4 + kt) * 64 + r) * 128) + ((ch ^ (r & 7)) * 16);
    *(uint4*)(g_aP + dst) = *(uint4*)hv;
}

// ---------------------------------------------------------------------------
// Kernel 1: fp16 mma gates GEMM, bulk-copy loaded, double-buffered, ldmatrix
// fragment loads, 4 CTAs/SM (32 warps/SM). CTA: 256 threads, tile 64 rows x
// 128 interleaved-cols; 8 warps 2(M) x 4(N), warp tile 32x32.
// ---------------------------------------------------------------------------
#define STG_A 8192
#define STG_W 16384
#define STG_B (STG_A + STG_W)          // 24576
#define SM_ST0 1024
#define SMEM_TOT (SM_ST0 + 2 * STG_B)  // 50176

__global__ __launch_bounds__(256, 4) void gates_mma_kernel(
    const float* __restrict__ act, const int* __restrict__ pos,
    const float* __restrict__ big, const float* __restrict__ brg)
{
    extern __shared__ char smc[];
    const uint32_t sb = smem_u32(smc);

    const int tid = threadIdx.x;
    const int wid = tid >> 5, lane = tid & 31;
    const int g = lane >> 2, t = lane & 3;
    const int wm = wid & 1;        // 32-row slab
    const int wn = wid >> 1;       // 0..3 -> 32-col slab (16 j's)
    const int h  = blockIdx.z;
    const int nq = blockIdx.y;
    const int tile = blockIdx.x;
    const int rb = tile * 64;

    if (tid == 0) { MBAR_INIT(sb + 0, 1); MBAR_INIT(sb + 8, 1); }
    __syncthreads();

    const char* aSrc = g_aP + ((size_t)(tile * Hh + h) * 4) * STG_A;
    const char* wSrc = g_wP + ((size_t)(h * 4 + nq) * 4) * STG_W;
    if (tid == 0) {
        #pragma unroll
        for (int s = 0; s < 2; s++) {
            uint32_t mb = sb + s * 8;
            uint32_t ds = sb + SM_ST0 + s * STG_B;
            MBAR_EXPECT(mb, STG_B);
            BULK_G2S(ds,         aSrc + (size_t)s * STG_A, STG_A, mb);
            BULK_G2S(ds + STG_A, wSrc + (size_t)s * STG_W, STG_W, mb);
        }
    }

    float acc[2][4][4];
    #pragma unroll
    for (int mt = 0; mt < 2; mt++)
        #pragma unroll
        for (int nt = 0; nt < 4; nt++)
            #pragma unroll
            for (int c = 0; c < 4; c++) acc[mt][nt][c] = 0.0f;

    // ldmatrix per-lane address components
    const int jA    = lane & 7;               // row-within-8 this lane addresses
    const int i8    = (lane >> 3) & 1;        // A: row-half select
    const int hi16A = ((lane >> 4) & 1) << 4; // A: k-chunk select (byte XOR)
    const uint32_t rowA0 = (uint32_t)(wm * 32 + i8 * 8 + jA) * 128;        // mt=0
    const uint32_t rowB  = (uint32_t)(wn * 32 + (lane >> 3) * 8 + jA) * 128;

    #pragma unroll
    for (int kt = 0; kt < 4; kt++) {
        MBAR_WAIT(sb + (kt & 1) * 8, (kt >> 1) & 1);
        const uint32_t Abase = sb + SM_ST0 + (kt & 1) * STG_B;
        const uint32_t Wbase = Abase + STG_A;

        #pragma unroll
        for (int k16 = 0; k16 < 4; k16++) {
            const uint32_t b0 = (uint32_t)(((k16 * 2) ^ jA) << 4);
            uint32_t af0[4], af1[4], blo[4], bhi[4];
            ldm_x4(af0, Abase + rowA0 + (b0 ^ hi16A));
            ldm_x4(af1, Abase + rowA0 + 2048 + (b0 ^ hi16A));
            ldm_x4(blo, Wbase + rowB + b0);
            ldm_x4(bhi, Wbase + rowB + (b0 ^ 16));
            #pragma unroll
            for (int nt = 0; nt < 4; nt++) {
                mma_f16(acc[0][nt], af0, blo[nt], bhi[nt]);
                mma_f16(acc[1][nt], af1, blo[nt], bhi[nt]);
            }
        }
        if (kt < 2) {   // buffer kt free -> issue stage kt+2 into it
            __syncthreads();
            if (tid == 0) {
                uint32_t mb = sb + (kt & 1) * 8;
                uint32_t ds = sb + SM_ST0 + (kt & 1) * STG_B;
                MBAR_EXPECT(mb, STG_B);
                BULK_G2S(ds,         aSrc + (size_t)(kt + 2) * STG_A, STG_A, mb);
                BULK_G2S(ds + STG_A, wSrc + (size_t)(kt + 2) * STG_W, STG_W, mb);
            }
        }
    }

    // -------- fused epilogue --------
    // thread's j for nt: j = nq*64 + wn*16 + nt*4 + t ; gates (c0,c1)/(c2,c3)
    float bi[4], br[4], sp4[4];
    const int dg0 = h * BW + nq * 64 + wn * 16 + t;
    #pragma unroll
    for (int nt = 0; nt < 4; nt++) {
        int dg = dg0 + nt * 4;
        bi[nt]  = big[dg];
        br[nt]  = brg[dg];
        sp4[nt] = g_sp[dg];
    }

    #pragma unroll
    for (int mt = 0; mt < 2; mt++) {
        int r1 = rb + wm * 32 + mt * 16 + g;
        int r2 = r1 + 8;
        bool rs1 = (pos[r1] == 0);
        bool rs2 = (pos[r2] == 0);
        const float* a1p = act + (size_t)r1 * Dd;
        const float* a2p = act + (size_t)r2 * Dd;
        float2* o1 = g_ax + (size_t)r1 * Dd;
        float2* o2 = g_ax + (size_t)r2 * Dd;
        #pragma unroll
        for (int nt = 0; nt < 4; nt++) {
            int dg = dg0 + nt * 4;
            {
                float ig = 1.0f / (1.0f + __expf(-(acc[mt][nt][0] + bi[nt])));
                float rg = 1.0f / (1.0f + __expf(-(acc[mt][nt][1] + br[nt])));
                float a  = __expf(-8.0f * rg * sp4[nt]);
                float m  = sqrtf(fmaxf(fmaf(-a, a, 1.0f), 0.0f));
                float xn = a1p[dg] * ig * (rs1 ? 1.0f : m);
                o1[dg] = make_float2(rs1 ? 0.0f : a, xn);
            }
            {
                float ig = 1.0f / (1.0f + __expf(-(acc[mt][nt][2] + bi[nt])));
                float rg = 1.0f / (1.0f + __expf(-(acc[mt][nt][3] + br[nt])));
                float a  = __expf(-8.0f * rg * sp4[nt]);
                float m  = sqrtf(fmaxf(fmaf(-a, a, 1.0f), 0.0f));
                float xn = a2p[dg] * ig * (rs2 ? 1.0f : m);
                o2[dg] = make_float2(rs2 ? 0.0f : a, xn);
            }
        }
    }
}

// ---------------------------------------------------------------------------
// Kernel 2a: per-chunk local scan -> (product, local final state)
// ---------------------------------------------------------------------------
__global__ __launch_bounds__(128) void scan_part_kernel() {
    int ch = blockIdx.x * 128 + threadIdx.x;
    int c  = blockIdx.y;
    int b  = ch / Dd;
    int d  = ch - b * Dd;
    size_t base = (size_t)b * Ts * Dd + (size_t)c * CH * Dd + d;

    float P = 1.0f, hacc = 0.0f;
    #pragma unroll 1
    for (int t0 = 0; t0 < CH; t0 += 8) {
        float2 v[8];
        #pragma unroll
        for (int u = 0; u < 8; u++) v[u] = g_ax[base + (size_t)(t0 + u) * Dd];
        #pragma unroll
        for (int u = 0; u < 8; u++) {
            P *= v[u].x;
            hacc = fmaf(v[u].x, hacc, v[u].y);
        }
    }
    g_P[c * NCHAN + ch] = P;
    g_h[c * NCHAN + ch] = hacc;
}

// ---------------------------------------------------------------------------
// Kernel 2b: cross-chunk recurrence
// ---------------------------------------------------------------------------
__global__ __launch_bounds__(128) void scan_link_kernel() {
    int ch = blockIdx.x * 128 + threadIdx.x;
    float H = 0.0f;
    #pragma unroll
    for (int c = 0; c < NCH; c++) {
        g_H[c * NCHAN + ch] = H;
        H = fmaf(g_P[c * NCHAN + ch], H, g_h[c * NCHAN + ch]);
    }
}

// ---------------------------------------------------------------------------
// Kernel 2c: seeded local scan, write output
// ---------------------------------------------------------------------------
__global__ __launch_bounds__(128) void scan_final_kernel(float* __restrict__ out) {
    int ch = blockIdx.x * 128 + threadIdx.x;
    int c  = blockIdx.y;
    int b  = ch / Dd;
    int d  = ch - b * Dd;
    size_t base = (size_t)b * Ts * Dd + (size_t)c * CH * Dd + d;

    float hacc = g_H[c * NCHAN + ch];
    #pragma unroll 1
    for (int t0 = 0; t0 < CH; t0 += 8) {
        float2 v[8];
        #pragma unroll
        for (int u = 0; u < 8; u++) v[u] = g_ax[base + (size_t)(t0 + u) * Dd];
        #pragma unroll
        for (int u = 0; u < 8; u++) {
            hacc = fmaf(v[u].x, hacc, v[u].y);
            out[base + (size_t)(t0 + u) * Dd] = hacc;
        }
    }
}

// ---------------------------------------------------------------------------
extern "C" void kernel_launch(void* const* d_in, const int* in_sizes, int n_in,
                              void* d_out, int out_size) {
    const float* act = (const float*)d_in[0];
    const int*   pos = (const int*)  d_in[1];
    const float* wig = (const float*)d_in[2];
    const float* big = (const float*)d_in[3];
    const float* wrg = (const float*)d_in[4];
    const float* brg = (const float*)d_in[5];
    const float* rp  = (const float*)d_in[6];
    float* out = (float*)d_out;

    static int smem_set = 0;
    if (!smem_set) {
        cudaFuncSetAttribute(gates_mma_kernel,
                             cudaFuncAttributeMaxDynamicSharedMemorySize, SMEM_TOT);
        smem_set = 1;
    }

    sp_kernel<<<(Dd + 255) / 256, 256>>>(rp);
    wt_kernel<<<(Hh * 4 * 4 * 128 * 8) / 256, 256>>>(wig, wrg);
    cvt_kernel<<<Mrows, 320>>>(act);

    dim3 grid(Mrows / 64, 4, Hh);    // (256, 4, 10) = 10240 CTAs
    gates_mma_kernel<<<grid, 256, SMEM_TOT>>>(act, pos, big, brg);

    dim3 sgrid(NCHAN / 128, NCH);    // (80, 32)
    scan_part_kernel<<<sgrid, 128>>>();
    scan_link_kernel<<<NCHAN / 128, 128>>>();
    scan_final_kernel<<<sgrid, 128>>>(out);
}